// round 5
// baseline (speedup 1.0000x reference)
#include <cuda_runtime.h>
#include <cuda_bf16.h>
#include <stdint.h>
#include <math.h>

#define EPSF 1e-8f
#define DD 128               // d
#define KPAD 10048           // 628*16 padded K (= problem N)
#define NCHUNKS 157          // 64-k chunks
#define EPAD 5120
#define EPITCH 5120          // 40*128
#define NSLMAX 8

// ---------------- static device scratch (no allocation) ----------------------
static __device__ __align__(256) __nv_bfloat16 g_FsT[DD * KPAD];       // Fs^T K-major bf16
static __device__ __align__(256) float g_Mpart[NSLMAX * DD * EPITCH];  // 21 MB partials
static __device__ float g_deinv[EPAD];
static __device__ float g_blocksum[2560];
static __device__ float g_f2sum[640];

// ---------------- helpers ----------------------------------------------------
__device__ __forceinline__ uint32_t smem_u32(const void* p) {
    uint32_t a;
    asm("{ .reg .u64 t; cvta.to.shared.u64 t, %1; cvt.u32.u64 %0, t; }"
        : "=r"(a) : "l"(p));
    return a;
}
#define SWZ(o) ((o) ^ (((o) >> 3) & 0x70))

__device__ __forceinline__ void sts128(uint32_t addr, uint32_t a, uint32_t b,
                                       uint32_t c, uint32_t d) {
    asm volatile("st.shared.v4.b32 [%0], {%1,%2,%3,%4};"
                 :: "r"(addr), "r"(a), "r"(b), "r"(c), "r"(d) : "memory");
}
#define CPA16(dst, src) \
    asm volatile("cp.async.ca.shared.global [%0], [%1], 16;" \
                 :: "r"(dst), "l"(src) : "memory")
#define CPA_COMMIT() asm volatile("cp.async.commit_group;" ::: "memory")
#define CPA_WAIT0()  asm volatile("cp.async.wait_group 0;" ::: "memory")

#define LDSM4(r, addr) \
    asm volatile("ldmatrix.sync.aligned.m8n8.x4.shared.b16 {%0,%1,%2,%3}, [%4];" \
                 : "=r"((r)[0]), "=r"((r)[1]), "=r"((r)[2]), "=r"((r)[3]) : "r"(addr))
#define LDSM4T(r, addr) \
    asm volatile("ldmatrix.sync.aligned.m8n8.x4.trans.shared.b16 {%0,%1,%2,%3}, [%4];" \
                 : "=r"((r)[0]), "=r"((r)[1]), "=r"((r)[2]), "=r"((r)[3]) : "r"(addr))

__device__ __forceinline__ void mma16816(float* c, const uint32_t* a,
                                         uint32_t b0, uint32_t b1) {
    asm volatile(
        "mma.sync.aligned.m16n8k16.row.col.f32.bf16.bf16.f32 "
        "{%0,%1,%2,%3}, {%4,%5,%6,%7}, {%8,%9}, {%0,%1,%2,%3};"
        : "+f"(c[0]), "+f"(c[1]), "+f"(c[2]), "+f"(c[3])
        : "r"(a[0]), "r"(a[1]), "r"(a[2]), "r"(a[3]), "r"(b0), "r"(b1));
}

// ---------------- prep: FsT transpose + sum(F^2) + deinv ---------------------
__global__ void __launch_bounds__(256, 4)
prep_fst(const float* __restrict__ F, const float* __restrict__ Dv,
         const float* __restrict__ De, int Nn, int Ee) {
    __shared__ __nv_bfloat16 s[16][132];
    __shared__ float red[256];
    __shared__ float dvis[16];
    const int t = threadIdx.x;
    const int n0 = blockIdx.x * 16;

    if (t < 16) {
        int n = n0 + t;
        dvis[t] = (n < Nn) ? rsqrtf(Dv[(size_t)n * Nn + n] + EPSF) : 0.f;
    }
    // fused deinv fill (first 20 blocks)
    if (blockIdx.x < 20) {
        int e = blockIdx.x * 256 + t;
        g_deinv[e] = (e < Ee) ? 1.f / (De[(size_t)e * Ee + e] + EPSF) : 0.f;
    }
    __syncthreads();

    float f2 = 0.f;
    #pragma unroll
    for (int i = 0; i < 2; ++i) {
        int g = t + 256 * i;          // 512 float4 slots (16 n x 32)
        int nl = g >> 5;
        int d4 = (g & 31) * 4;
        int n = n0 + nl;
        float4 v = make_float4(0.f, 0.f, 0.f, 0.f);
        float sc = 0.f;
        if (n < Nn) { v = *(const float4*)&F[(size_t)n * DD + d4]; sc = dvis[nl]; }
        f2 += v.x * v.x + v.y * v.y + v.z * v.z + v.w * v.w;
        s[nl][d4 + 0] = __float2bfloat16(v.x * sc);
        s[nl][d4 + 1] = __float2bfloat16(v.y * sc);
        s[nl][d4 + 2] = __float2bfloat16(v.z * sc);
        s[nl][d4 + 3] = __float2bfloat16(v.w * sc);
    }
    __syncthreads();
    {   // transposed write: thread -> (d, 8 n values) = one uint4
        int d = t >> 1;
        int nh = (t & 1) * 8;
        uint32_t w[4];
        #pragma unroll
        for (int j = 0; j < 4; ++j) {
            __nv_bfloat162 p;
            p.x = s[nh + 2 * j][d];
            p.y = s[nh + 2 * j + 1][d];
            w[j] = *(uint32_t*)&p;
        }
        *(uint4*)&g_FsT[(size_t)d * KPAD + n0 + nh] = make_uint4(w[0], w[1], w[2], w[3]);
    }
    red[t] = f2;
    __syncthreads();
    #pragma unroll
    for (int s2 = 128; s2 > 0; s2 >>= 1) {
        if (t < s2) red[t] += red[t + s2];
        __syncthreads();
    }
    if (t == 0) g_f2sum[blockIdx.x] = red[0];
}

// ---------------- GEMM: mma.sync bf16, CTA 128(d) x 128(e), 512 thr ----------
// grid = 296 CTAs: etiles 0..15 -> 8 K-slices, etiles 16..39 -> 7 K-slices.
// Dynamic SMEM 64KB: A 2x16KB @0, B 2x16KB @32768 (each B = lo 8KB + hi 8KB).
__global__ void __launch_bounds__(512, 1)
gemm_kernel(const float* __restrict__ H, int Nn, int Ee) {
    extern __shared__ __align__(1024) char smem[];
    const uint32_t sb = smem_u32(smem);

    const int t = threadIdx.x;
    const int lane = t & 31;
    const int wid = t >> 5;            // 0..15
    const int wm = wid & 3;            // 4 m-warps
    const int wn = wid >> 2;           // 4 n-warps (32 e each)
    const int m0 = wm * 32;
    const int ew0 = (wn >> 1) * 64 + (wn & 1) * 32;   // e offset within 128-tile
    const uint32_t bHalfSel = (wn >> 1) ? 8192u : 0u; // which 64e half
    const int ewin = (wn & 1) * 32;                   // e offset within half

    // ---- work mapping ----
    const int bid = blockIdx.x;
    int et, sl, nsl;
    if (bid < 128) { et = bid >> 3;        sl = bid & 7; nsl = 8; }
    else           { int r = bid - 128; et = 16 + r / 7; sl = r % 7; nsl = 7; }
    const int e0 = et * 128;
    const int c0 = (sl * NCHUNKS) / nsl;
    const int c1 = ((sl + 1) * NCHUNKS) / nsl;
    const int nch = c1 - c0;
    const bool tail = (e0 + 128 > Ee);

    const int krow = t >> 3;           // 0..63 (k row in chunk)
    const int ecol = (t & 7) * 16;     // 16 e per thread
    const int eloc = ecol & 63;
    const uint32_t stsHalf = (ecol >= 64) ? 8192u : 0u;

    float acc[2][4][4];
    #pragma unroll
    for (int i = 0; i < 2; ++i)
        #pragma unroll
        for (int j = 0; j < 4; ++j)
            #pragma unroll
            for (int q = 0; q < 4; ++q) acc[i][j][q] = 0.f;

    const int aRow = (lane & 15);
    const int aKh  = (lane >> 4) * 8;
    const int bKr  = (lane & 15);
    const int bNc  = (lane >> 4) * 8;

    uint32_t w[8];                     // converted B staging (bf16x2)

#define LOAD_A(buf, chunk) do {                                              \
        int _cg = (chunk);                                                   \
        _Pragma("unroll")                                                    \
        for (int _i = 0; _i < 2; ++_i) {                                     \
            int pos = t + 512 * _i;                                          \
            int row = pos >> 3;                                              \
            int cc  = pos & 7;                                               \
            const __nv_bfloat16* src = &g_FsT[(size_t)row * KPAD + _cg * 64 + cc * 8]; \
            uint32_t off = (uint32_t)(row * 128 + cc * 16);                  \
            CPA16((buf) + SWZ(off), src);                                    \
        }                                                                    \
    } while (0)

#define LDG_H(chunk) do {                                                    \
        int _n = (chunk) * 64 + krow;                                        \
        bool _v = _n < Nn;                                                   \
        const float* _hr = H + (size_t)_n * Ee;                              \
        _Pragma("unroll")                                                    \
        for (int _j = 0; _j < 4; ++_j) {                                     \
            float4 f;                                                        \
            if (!tail) {                                                     \
                f = _v ? *(const float4*)&_hr[e0 + ecol + 4 * _j]            \
                       : make_float4(0.f, 0.f, 0.f, 0.f);                    \
            } else {                                                         \
                int _e = e0 + ecol + 4 * _j;                                 \
                f.x = (_v && _e + 0 < Ee) ? _hr[_e + 0] : 0.f;               \
                f.y = (_v && _e + 1 < Ee) ? _hr[_e + 1] : 0.f;               \
                f.z = (_v && _e + 2 < Ee) ? _hr[_e + 2] : 0.f;               \
                f.w = (_v && _e + 3 < Ee) ? _hr[_e + 3] : 0.f;               \
            }                                                                \
            __nv_bfloat162 p0 = __floats2bfloat162_rn(f.x, f.y);             \
            __nv_bfloat162 p1 = __floats2bfloat162_rn(f.z, f.w);             \
            w[2 * _j]     = *(uint32_t*)&p0;                                 \
            w[2 * _j + 1] = *(uint32_t*)&p1;                                 \
        }                                                                    \
    } while (0)

#define STS_H(bbase) do {                                                    \
        uint32_t reg = (bbase) + stsHalf;                                    \
        uint32_t off = (uint32_t)(krow * 128 + eloc * 2);                    \
        sts128(reg + SWZ(off),      w[0], w[1], w[2], w[3]);                 \
        sts128(reg + SWZ(off + 16), w[4], w[5], w[6], w[7]);                 \
    } while (0)

#define LOAD_FRAG(fa, fb, abuf, breg, k0) do {                               \
        _Pragma("unroll")                                                    \
        for (int _i = 0; _i < 2; ++_i) {                                     \
            uint32_t off = (uint32_t)((m0 + _i * 16 + aRow) * 128            \
                                      + ((k0) + aKh) * 2);                   \
            LDSM4((fa) + 4 * _i, (abuf) + SWZ(off));                         \
        }                                                                    \
        _Pragma("unroll")                                                    \
        for (int _jb = 0; _jb < 2; ++_jb) {                                  \
            uint32_t off = (uint32_t)(((k0) + bKr) * 128                     \
                                      + (ewin + _jb * 16 + bNc) * 2);        \
            LDSM4T((fb) + 4 * _jb, (breg) + SWZ(off));                       \
        }                                                                    \
    } while (0)

#define DO_MMAS(fa, fb) do {                                                 \
        _Pragma("unroll")                                                    \
        for (int _i = 0; _i < 2; ++_i)                                       \
            _Pragma("unroll")                                                \
            for (int _j = 0; _j < 4; ++_j)                                   \
                mma16816(acc[_i][_j], (fa) + 4 * _i,                         \
                         (fb)[(_j >> 1) * 4 + (_j & 1) * 2],                 \
                         (fb)[(_j >> 1) * 4 + (_j & 1) * 2 + 1]);            \
    } while (0)

    // ---- pipeline (double-buffered smem + double-buffered fragments) ----
    LOAD_A(sb, c0);
    CPA_COMMIT();
    LDG_H(c0);
    CPA_WAIT0();
    STS_H(sb + 32768);
    __syncthreads();

    for (int cc = 0; cc < nch; ++cc) {
        const int b = cc & 1;
        const uint32_t aCur = sb + b * 16384;
        const uint32_t bCur = sb + 32768 + b * 16384 + bHalfSel;
        const uint32_t aNxt = sb + (b ^ 1) * 16384;
        const uint32_t bNxt = sb + 32768 + (b ^ 1) * 16384;
        const bool has = (cc + 1) < nch;
        if (has) {
            LOAD_A(aNxt, c0 + cc + 1);
            CPA_COMMIT();
            LDG_H(c0 + cc + 1);
        }
        // compute with fragment double buffering
        {
            uint32_t fa[2][8], fb[2][8];
            LOAD_FRAG(fa[0], fb[0], aCur, bCur, 0);
            #pragma unroll
            for (int k0 = 0; k0 < 4; ++k0) {
                if (k0 < 3)
                    LOAD_FRAG(fa[(k0 + 1) & 1], fb[(k0 + 1) & 1], aCur, bCur,
                              (k0 + 1) * 16);
                DO_MMAS(fa[k0 & 1], fb[k0 & 1]);
            }
        }
        if (has) {
            CPA_WAIT0();
            STS_H(bNxt);
        }
        __syncthreads();
    }

    // ---- write partials: g_Mpart[sl][d][e] ----
    #pragma unroll
    for (int i = 0; i < 2; ++i) {
        #pragma unroll
        for (int j = 0; j < 4; ++j) {
            int d = m0 + i * 16 + (lane >> 2);
            int e = e0 + ew0 + j * 8 + (lane & 3) * 2;
            size_t base = ((size_t)(sl * DD + d)) * EPITCH + e;
            *(float2*)&g_Mpart[base] = make_float2(acc[i][j][0], acc[i][j][1]);
            *(float2*)&g_Mpart[base + (size_t)8 * EPITCH] =
                make_float2(acc[i][j][2], acc[i][j][3]);
        }
    }
}

// ---------------- pass 3: S partials = sum deinv * (sum_sl M)^2 --------------
// grid 2560: block -> (d = bid/20, e-range (bid%20)*256). One (d,e) per thread.
__global__ void __launch_bounds__(256, 8)
pass3_kernel() {
    __shared__ float r[256];
    const int t = threadIdx.x;
    const int d = blockIdx.x / 20;
    const int e = (blockIdx.x % 20) * 256 + t;
    const int nsl = ((e >> 7) < 16) ? 8 : 7;
    float v = 0.f;
    #pragma unroll
    for (int j = 0; j < NSLMAX; ++j)
        if (j < nsl) v += g_Mpart[((size_t)(j * DD + d)) * EPITCH + e];
    r[t] = v * v * g_deinv[e];
    __syncthreads();
    #pragma unroll
    for (int s = 128; s > 0; s >>= 1) {
        if (t < s) r[t] += r[t + s];
        __syncthreads();
    }
    if (t == 0) g_blocksum[blockIdx.x] = r[0];
}

// ---------------- final combine ----------------------------------------------
__global__ void final_kernel(float* __restrict__ out, int Nn, int nsum, int nprep) {
    __shared__ float red[256];
    int t = threadIdx.x;
    float acc = 0.f;
    for (int i = t; i < nprep; i += 256) acc += g_f2sum[i];
    for (int i = t; i < nsum; i += 256) acc -= g_blocksum[i];
    red[t] = acc;
    __syncthreads();
    #pragma unroll
    for (int s = 128; s > 0; s >>= 1) {
        if (t < s) red[t] += red[t + s];
        __syncthreads();
    }
    if (t == 0) out[0] = red[0] / (float)Nn;
}

// ---------------- launch ------------------------------------------------------
extern "C" void kernel_launch(void* const* d_in, const int* in_sizes, int n_in,
                              void* d_out, int out_size) {
    const float* F  = (const float*)d_in[0];   // [N,128]
    const float* H  = (const float*)d_in[1];   // [N,E]
    const float* Dv = (const float*)d_in[2];   // [N,N]
    const float* De = (const float*)d_in[3];   // [E,E]
    float* out = (float*)d_out;

    int Nn = in_sizes[0] / DD;                 // 10000
    int Ee = in_sizes[1] / Nn;                 // 5000
    int nprep = KPAD / 16;                     // 628

    cudaFuncSetAttribute(gemm_kernel, cudaFuncAttributeMaxDynamicSharedMemorySize,
                         65536);

    prep_fst<<<nprep, 256>>>(F, Dv, De, Nn, Ee);
    gemm_kernel<<<296, 512, 65536>>>(H, Nn, Ee);
    pass3_kernel<<<2560, 256>>>();
    final_kernel<<<1, 256>>>(out, Nn, 2560, nprep);
}